// round 16
// baseline (speedup 1.0000x reference)
#include <cuda_runtime.h>
#include <cstdint>

// ============================================================================
// out[m,n] = scale * sum_k x[m,k] * w[n,k]
//   M = 8192, K = 4096, N = 11008; x fp32, w int32 (int8-valued), scale fp32.
//
// Base-sm_103 ptxas target: portable compute_80 ISA only.
// R15: double-int8 path. Legacy f16-fp32acc mma is pipe-saturated at
// ~1024 FLOP/cyc/SM (284 TF/s measured = floor). int8 mma.sync m16n8k32 is
// expected at 4x that rate. Split x = 2^-11 * (128*h + l), h,l int8 (15-bit),
// W exact int8 => two s8 GEMMs with exact s32 accumulation.
//   rel_err ~ 1.4e-4 (x quantization only).
//
// Prepack kernels write FRAGMENT-MAJOR layouts (each lane's mma fragment is
// contiguous), so the GEMM uses plain LDS.128/LDS.64 (no ldmatrix) and
// cp.async copies verbatim blocks.
// ============================================================================

static constexpr int M = 8192;
static constexpr int N = 11008;
static constexpr int K = 4096;
static constexpr int KS = K / 32;            // 128 k32-steps
static constexpr int TM = 64;                // CTA tile M
static constexpr int TN = 128;               // CTA tile N
static constexpr int NCHUNK = K / 64;        // 64 chunks (2 k32-steps each)
static constexpr int MT2 = M / TM;           // 128
static constexpr int NT2 = N / TN;           // 86
static constexpr int NSTAGE = 4;
// Stage layout: [Ah 4KB (8 blk x 512B)][Al 4KB][B 8KB (32 blk x 256B)]
static constexpr int STAGE_BYTES = 16384;
static constexpr int SMEM_BYTES = NSTAGE * STAGE_BYTES;   // 64KB (x2 CTA/SM)
static constexpr int GROUP_M = 16;           // L2 rasterization group

// Fragment-major scratch (device-global scratch: sanctioned no-malloc path)
// A planes: [mtile(512)][kstep(128)][lane(32)][16B]   = 32MB each
// B:        [ntile(1376)][kstep(128)][lane(32)][8B]   = 43MB
static __device__ __align__(256) uint8_t g_Ah[(size_t)M * K];
static __device__ __align__(256) uint8_t g_Al[(size_t)M * K];
static __device__ __align__(256) uint8_t g_Bw[(size_t)N * K];

// ---------------------------------------------------------------------------
// Helpers (all compute_80-legal)
// ---------------------------------------------------------------------------
__device__ __forceinline__ uint32_t smem_u32(const void* p) {
    uint32_t a;
    asm("{ .reg .u64 t; cvta.to.shared.u64 t, %1; cvt.u32.u64 %0, t; }"
        : "=r"(a) : "l"(p));
    return a;
}
__device__ __forceinline__ void cp16(uint32_t smem_dst, const void* gsrc) {
    asm volatile("cp.async.cg.shared.global [%0], [%1], 16;"
                 :: "r"(smem_dst), "l"(gsrc));
}
__device__ __forceinline__ void lds128(uint32_t* r, uint32_t addr) {
    asm volatile("ld.shared.v4.u32 {%0,%1,%2,%3}, [%4];"
                 : "=r"(r[0]), "=r"(r[1]), "=r"(r[2]), "=r"(r[3]) : "r"(addr));
}
__device__ __forceinline__ void lds64(uint32_t* r, uint32_t addr) {
    asm volatile("ld.shared.v2.u32 {%0,%1}, [%2];"
                 : "=r"(r[0]), "=r"(r[1]) : "r"(addr));
}
__device__ __forceinline__ void mma_s8(int* c, const uint32_t* a,
                                       const uint32_t* b) {
    asm volatile(
        "mma.sync.aligned.m16n8k32.row.col.s32.s8.s8.s32 "
        "{%0,%1,%2,%3}, {%4,%5,%6,%7}, {%8,%9}, {%0,%1,%2,%3};"
        : "+r"(c[0]), "+r"(c[1]), "+r"(c[2]), "+r"(c[3])
        : "r"(a[0]), "r"(a[1]), "r"(a[2]), "r"(a[3]),
          "r"(b[0]), "r"(b[1]));
}
__device__ __forceinline__ uint32_t pack4(int b0, int b1, int b2, int b3) {
    return (uint32_t)(b0 & 0xFF) | ((uint32_t)(b1 & 0xFF) << 8) |
           ((uint32_t)(b2 & 0xFF) << 16) | ((uint32_t)(b3 & 0xFF) << 24);
}

// ---------------------------------------------------------------------------
// Prepack A: x fp32 -> 15-bit fixed point -> (h, l) int8 planes, frag-major.
// thread <-> (mtile, kstep, lane); lane: g = lane>>2 (row), t = lane&3 (k/4).
// Fragment regs: r0=(row g, k 4t..), r1=(g+8, 4t..), r2=(g, 16+4t..),
//                r3=(g+8, 16+4t..)  -> one uint4 write per plane.
// ---------------------------------------------------------------------------
__device__ __forceinline__ void quant4(float4 v, uint32_t& h, uint32_t& l) {
    int fx[4], hh[4], ll[4];
    float f[4] = {v.x, v.y, v.z, v.w};
#pragma unroll
    for (int i = 0; i < 4; i++) {
        float s = fminf(fmaxf(f[i] * 2048.0f, -16384.0f), 16319.0f);
        fx[i] = __float2int_rn(s);
        hh[i] = (fx[i] + 64) >> 7;           // [-128,127]
        ll[i] = fx[i] - (hh[i] << 7);        // [-64,63]
    }
    h = pack4(hh[0], hh[1], hh[2], hh[3]);
    l = pack4(ll[0], ll[1], ll[2], ll[3]);
}

__global__ void prepack_x_kernel(const float4* __restrict__ x) {
    uint32_t idx = blockIdx.x * blockDim.x + threadIdx.x;   // < 2,097,152
    uint32_t tks = idx >> 5;                 // mtile*KS + kstep
    uint32_t lane = idx & 31;
    uint32_t mt = tks / KS, ks = tks % KS;
    uint32_t g = lane >> 2, t = lane & 3;
    uint32_t r0 = mt * 16 + g;
    uint32_t c0 = ks * 32 + t * 4;           // element index (fp32)
    const float4* xr0 = x + ((size_t)r0 * K + c0) / 4;
    const float4* xr1 = x + ((size_t)(r0 + 8) * K + c0) / 4;
    uint4 H, L;
    quant4(xr0[0], H.x, L.x);
    quant4(xr1[0], H.y, L.y);
    quant4(xr0[4], H.z, L.z);                // +16 elements = +4 float4
    quant4(xr1[4], H.w, L.w);
    size_t o = (size_t)(tks * 32 + lane);
    reinterpret_cast<uint4*>(g_Ah)[o] = H;
    reinterpret_cast<uint4*>(g_Al)[o] = L;
}

// Prepack W: int32 (int8-valued) -> frag-major int8 B.
// thread <-> (ntile, kstep, lane); b0 = W[n=g][k 4t..], b1 = W[n=g][16+4t..]
__global__ void prepack_w_kernel(const int4* __restrict__ w) {
    uint32_t idx = blockIdx.x * blockDim.x + threadIdx.x;   // < 5,636,096
    uint32_t tks = idx >> 5;
    uint32_t lane = idx & 31;
    uint32_t nt = tks / KS, ks = tks % KS;
    uint32_t g = lane >> 2, t = lane & 3;
    uint32_t n = nt * 8 + g;
    uint32_t c0 = ks * 32 + t * 4;
    int4 v0 = w[((size_t)n * K + c0) / 4];
    int4 v1 = w[((size_t)n * K + c0 + 16) / 4];
    uint2 B;
    B.x = pack4(v0.x, v0.y, v0.z, v0.w);
    B.y = pack4(v1.x, v1.y, v1.z, v1.w);
    reinterpret_cast<uint2*>(g_Bw)[(size_t)(tks * 32 + lane)] = B;
}

// ---------------------------------------------------------------------------
// GEMM: 256 threads, CTA tile 64x128, warps 2(M) x 4(N), warp tile 32x32.
// Dual s32 accumulators (h and l planes). 4-stage cp.async pipeline.
// ---------------------------------------------------------------------------
__global__ __launch_bounds__(256, 2)
void gemm_s8_kernel(const float* __restrict__ scale_ptr,
                    float* __restrict__ out) {
    extern __shared__ __align__(1024) char smem[];
    const uint32_t sbase = smem_u32(smem);
    const int tid = threadIdx.x;
    const int wid = tid >> 5;
    const int lane = tid & 31;

    // rasterization: groups of GROUP_M m-tiles across all n-tiles
    int bid = blockIdx.x;
    int g = bid / (GROUP_M * NT2);
    int r = bid % (GROUP_M * NT2);
    int nti = r / GROUP_M;
    int mti = g * GROUP_M + (r % GROUP_M);
    const int m0 = mti * TM;
    const int n0 = nti * TN;
    const uint32_t mt0t = (uint32_t)(mti * 4);    // first m16-tile index
    const uint32_t nt0t = (uint32_t)(nti * 16);   // first n8-tile index

    // ---- loader: 4 cp16 per thread per chunk (1 Ah, 1 Al, 2 B)
    // Ah/Al: seg = tid>>5 (mt=seg>>1, ksl=seg&1), off=(tid&31)*16
    const uint32_t segA = (uint32_t)(tid >> 5);
    const uint32_t offA = (uint32_t)((tid & 31) * 16);
    const uint8_t* srcAh = g_Ah +
        ((size_t)(mt0t + (segA >> 1)) * KS + (segA & 1)) * 512 + offA;
    const uint8_t* srcAl = g_Al +
        ((size_t)(mt0t + (segA >> 1)) * KS + (segA & 1)) * 512 + offA;
    // B units u = tid and tid+256
    const uint32_t u0 = (uint32_t)tid, u1 = (uint32_t)(tid + 256);
    const uint8_t* srcB0 = g_Bw +
        ((size_t)(nt0t + (u0 >> 4 >> 1)) * KS + ((u0 >> 4) & 1)) * 256 +
        (u0 & 15) * 16;
    const uint8_t* srcB1 = g_Bw +
        ((size_t)(nt0t + (u1 >> 4 >> 1)) * KS + ((u1 >> 4) & 1)) * 256 +
        (u1 & 15) * 16;
    const uint32_t dAh = (uint32_t)(tid * 16);
    const uint32_t dAl = (uint32_t)(4096 + tid * 16);
    const uint32_t dB0 = (uint32_t)(8192 + u0 * 16);
    const uint32_t dB1 = (uint32_t)(8192 + u1 * 16);

    auto load_chunk = [&](int c, int s) {
        const uint32_t so = sbase + (uint32_t)(s * STAGE_BYTES);
        const size_t da = (size_t)c * 1024;   // 2 k32-steps * 512B
        const size_t db = (size_t)c * 512;    // 2 k32-steps * 256B
        cp16(so + dAh, srcAh + da);
        cp16(so + dAl, srcAl + da);
        cp16(so + dB0, srcB0 + db);
        cp16(so + dB1, srcB1 + db);
        asm volatile("cp.async.commit_group;" ::: "memory");
    };

    // ---- compute-side addressing
    const int wm = wid >> 2;                  // 0..1
    const int wn = wid & 3;                   // 0..3
    const uint32_t aoff = (uint32_t)(lane * 16);
    const uint32_t boff = (uint32_t)(8192 + lane * 8);

    int acc_h[2][4][4], acc_l[2][4][4];
#pragma unroll
    for (int i = 0; i < 2; i++)
#pragma unroll
        for (int j = 0; j < 4; j++)
#pragma unroll
            for (int q = 0; q < 4; q++) { acc_h[i][j][q] = 0; acc_l[i][j][q] = 0; }

    load_chunk(0, 0);
    load_chunk(1, 1);
    load_chunk(2, 2);

    for (int c = 0; c < NCHUNK; c++) {
        const int s = c & 3;
        if (c <= NCHUNK - 3)
            asm volatile("cp.async.wait_group 2;" ::: "memory");
        else if (c == NCHUNK - 2)
            asm volatile("cp.async.wait_group 1;" ::: "memory");
        else
            asm volatile("cp.async.wait_group 0;" ::: "memory");
        __syncthreads();

        if (c + 3 < NCHUNK) load_chunk(c + 3, (c + 3) & 3);

        const uint32_t so = sbase + (uint32_t)(s * STAGE_BYTES);
#pragma unroll
        for (int ks = 0; ks < 2; ks++) {
            uint32_t ah[2][4], al[2][4], bf[4][2];
#pragma unroll
            for (int mt = 0; mt < 2; mt++) {
                uint32_t blk = (uint32_t)(((wm * 2 + mt) * 2 + ks) * 512);
                lds128(ah[mt], so + blk + aoff);
                lds128(al[mt], so + 4096 + blk + aoff);
            }
#pragma unroll
            for (int nt = 0; nt < 4; nt++) {
                uint32_t blk = (uint32_t)(((wn * 4 + nt) * 2 + ks) * 256);
                lds64(bf[nt], so + boff + blk);
            }
#pragma unroll
            for (int mt = 0; mt < 2; mt++)
#pragma unroll
                for (int nt = 0; nt < 4; nt++) {
                    mma_s8(acc_h[mt][nt], ah[mt], bf[nt]);
                    mma_s8(acc_l[mt][nt], al[mt], bf[nt]);
                }
        }
    }

    // ---- epilogue: v = (128*acc_h + acc_l) * scale * 2^-11
    const float scl = __ldg(scale_ptr) * (1.0f / 2048.0f);
    const int er = lane >> 2;
    const int ec = (lane & 3) * 2;
#pragma unroll
    for (int mt = 0; mt < 2; mt++) {
#pragma unroll
        for (int half = 0; half < 2; half++) {
            int m = m0 + wm * 32 + mt * 16 + half * 8 + er;
            float* orow = out + (size_t)m * N + n0 + wn * 32 + ec;
#pragma unroll
            for (int nt = 0; nt < 4; nt++) {
                float2 v;
                v.x = fmaf((float)acc_h[mt][nt][half * 2 + 0], 128.0f,
                           (float)acc_l[mt][nt][half * 2 + 0]) * scl;
                v.y = fmaf((float)acc_h[mt][nt][half * 2 + 1], 128.0f,
                           (float)acc_l[mt][nt][half * 2 + 1]) * scl;
                *reinterpret_cast<float2*>(orow + nt * 8) = v;
            }
        }
    }
}

// ---------------------------------------------------------------------------
// Launch
// ---------------------------------------------------------------------------
extern "C" void kernel_launch(void* const* d_in, const int* in_sizes, int n_in,
                              void* d_out, int out_size) {
    const float* x = (const float*)d_in[0];       // [4,2048,4096] fp32
    const int* w = (const int*)d_in[1];           // [11008,4096] int32
    const float* scale = (const float*)d_in[2];   // [1] fp32
    float* out = (float*)d_out;                   // [4,2048,11008] fp32
    (void)in_sizes; (void)n_in; (void)out_size;

    {
        uint32_t ta = (uint32_t)((M / 16) * KS * 32);   // 2,097,152
        uint32_t tb = (uint32_t)((N / 8) * KS * 32);    // 5,636,096
        prepack_x_kernel<<<ta / 256, 256>>>((const float4*)x);
        prepack_w_kernel<<<tb / 256, 256>>>((const int4*)w);
    }

    cudaFuncSetAttribute(gemm_s8_kernel,
                         cudaFuncAttributeMaxDynamicSharedMemorySize,
                         SMEM_BYTES);
    gemm_s8_kernel<<<MT2 * NT2, 256, SMEM_BYTES>>>(scale, out);
}

// round 17
// speedup vs baseline: 2.4503x; 2.4503x over previous
#include <cuda_runtime.h>
#include <cuda_fp16.h>
#include <cstdint>

// ============================================================================
// out[m,n] = scale * sum_k x[m,k] * w[n,k]
//   M = 8192, K = 4096, N = 11008; x fp32, w int32 (int8-valued), scale fp32.
//
// Base-sm_103 ptxas target: portable compute_80 ISA only
// (mma.sync m16n8k16 f16->f32, ldmatrix, cp.async). tcgen05 rejected by the
// harness toolchain; legacy int8 mma measured 3.7x SLOWER than f16 (R15).
//
// R16 vs R11 (2599 us):
//   - warp tile 32x64 -> 64x64 (bytes/mma 192 -> 128; smem pipe unloaded)
//   - CTA = 4 warps (128 thr), 2 CTAs/SM, 255 regs/thread available
//   - prepack fused into ONE kernel (fewer launches; aligns ncu onto GEMM)
// ============================================================================

static constexpr int M = 8192;
static constexpr int N = 11008;
static constexpr int K = 4096;
static constexpr int TM = 128;
static constexpr int TN = 128;
static constexpr int KC = 64;                 // K halves per chunk = 128B row
static constexpr int NCHUNK = K / KC;         // 64
static constexpr int MT = M / TM;             // 64
static constexpr int NT = N / TN;             // 86
static constexpr int NSTAGE = 3;
static constexpr int ROW_BYTES = KC * 2;                   // 128
static constexpr int TILE_BYTES = TM * ROW_BYTES;          // 16384
static constexpr int STAGE_BYTES = 2 * TILE_BYTES;         // 32768
static constexpr int SMEM_BYTES = NSTAGE * STAGE_BYTES;    // 98304 (x2 CTA/SM)
static constexpr int GROUP_M = 16;            // L2 rasterization group

// fp16 scratch (device-global scratch: the sanctioned no-malloc mechanism)
static __device__ __align__(256) __half g_Wh[(size_t)N * K]; // 90.2 MB
static __device__ __align__(256) __half g_Xh[(size_t)M * K]; // 67.1 MB

// ---------------------------------------------------------------------------
// Portable PTX helpers (all compute_80-legal)
// ---------------------------------------------------------------------------
__device__ __forceinline__ uint32_t smem_u32(const void* p) {
    uint32_t a;
    asm("{ .reg .u64 t; cvta.to.shared.u64 t, %1; cvt.u32.u64 %0, t; }"
        : "=r"(a) : "l"(p));
    return a;
}

__device__ __forceinline__ void cp16(uint32_t smem_dst, const void* gsrc) {
    asm volatile("cp.async.cg.shared.global [%0], [%1], 16;"
                 :: "r"(smem_dst), "l"(gsrc));
}

__device__ __forceinline__ void ldmatrix_x4(uint32_t& r0, uint32_t& r1,
                                            uint32_t& r2, uint32_t& r3,
                                            uint32_t addr) {
    asm volatile("ldmatrix.sync.aligned.m8n8.x4.shared.b16 {%0,%1,%2,%3}, [%4];"
                 : "=r"(r0), "=r"(r1), "=r"(r2), "=r"(r3) : "r"(addr));
}

__device__ __forceinline__ void mma_16816(float* c, const uint32_t* a,
                                          const uint32_t* b) {
    asm volatile(
        "mma.sync.aligned.m16n8k16.row.col.f32.f16.f16.f32 "
        "{%0,%1,%2,%3}, {%4,%5,%6,%7}, {%8,%9}, {%0,%1,%2,%3};"
        : "+f"(c[0]), "+f"(c[1]), "+f"(c[2]), "+f"(c[3])
        : "r"(a[0]), "r"(a[1]), "r"(a[2]), "r"(a[3]),
          "r"(b[0]), "r"(b[1]));
}

// ---------------------------------------------------------------------------
// Fused prepack kernel: blocks [0, XB) convert x, blocks [XB, XB+WB) convert w.
// ---------------------------------------------------------------------------
static constexpr unsigned XB = (unsigned)(((size_t)M * K / 4 + 255) / 256); // 32768
static constexpr unsigned WB = (unsigned)(((size_t)N * K / 4 + 255) / 256); // 44032

__global__ void prepack_kernel(const float4* __restrict__ x,
                               const int4* __restrict__ w) {
    unsigned b = blockIdx.x;
    if (b < XB) {
        size_t idx = (size_t)b * 256 + threadIdx.x;
        if (idx >= (size_t)M * K / 4) return;
        float4 v = x[idx];
        union { __half2 h2[2]; uint2 u2; } cv;
        cv.h2[0] = __floats2half2_rn(v.x, v.y);
        cv.h2[1] = __floats2half2_rn(v.z, v.w);
        reinterpret_cast<uint2*>(g_Xh)[idx] = cv.u2;
    } else {
        size_t idx = (size_t)(b - XB) * 256 + threadIdx.x;
        if (idx >= (size_t)N * K / 4) return;
        int4 v = w[idx];
        union { __half2 h2[2]; uint2 u2; } cv;
        cv.h2[0] = __halves2half2(__int2half_rn(v.x), __int2half_rn(v.y));
        cv.h2[1] = __halves2half2(__int2half_rn(v.z), __int2half_rn(v.w));
        reinterpret_cast<uint2*>(g_Wh)[idx] = cv.u2;
    }
}

// ---------------------------------------------------------------------------
// GEMM: 128 threads (4 warps), CTA tile 128x128, warp tile 64x64 (2x2 grid),
// 2 CTAs/SM. 3-stage cp.async pipeline, XOR-swizzled 128B rows.
//   smem byte (row, col) at row*128 + (col ^ ((row & 7) << 4)).
// ---------------------------------------------------------------------------
__global__ __launch_bounds__(128, 2)
void gemm_kernel(const float* __restrict__ scale_ptr, float* __restrict__ out) {
    extern __shared__ __align__(1024) char smem[];
    const uint32_t sbase = smem_u32(smem);
    const int tid = threadIdx.x;
    const int wid = tid >> 5;
    const int lane = tid & 31;

    // L2-friendly rasterization: groups of GROUP_M m-tiles across all n-tiles
    int bid = blockIdx.x;
    int g = bid / (GROUP_M * NT);
    int r = bid % (GROUP_M * NT);
    int nt_idx = r / GROUP_M;
    int mt_idx = g * GROUP_M + (r % GROUP_M);
    const int m0 = mt_idx * TM;
    const int n0 = nt_idx * TN;

    const float scl = __ldg(scale_ptr);

    // --- loader: thread t owns A row t and B row t (8x16B each per chunk)
    const char* gA = reinterpret_cast<const char*>(g_Xh + (size_t)(m0 + tid) * K);
    const char* gB = reinterpret_cast<const char*>(g_Wh + (size_t)(n0 + tid) * K);
    const uint32_t ld_xor = (uint32_t)((tid & 7) << 4);
    const uint32_t sA_row = sbase + (uint32_t)(tid * ROW_BYTES);
    const uint32_t sB_row = sA_row + (uint32_t)TILE_BYTES;

    auto load_chunk = [&](int c, int s) {
        const uint32_t so = (uint32_t)(s * STAGE_BYTES);
        const char* srcA = gA + (size_t)c * ROW_BYTES;
        const char* srcB = gB + (size_t)c * ROW_BYTES;
#pragma unroll
        for (int j = 0; j < 8; j++) {
            uint32_t sw = ((uint32_t)(j * 16)) ^ ld_xor;
            cp16(sA_row + so + sw, srcA + j * 16);
            cp16(sB_row + so + sw, srcB + j * 16);
        }
        asm volatile("cp.async.commit_group;" ::: "memory");
    };

    // --- warp tile coordinates: 2x2 grid of 64x64 tiles
    const int warp_m = (wid & 1) * 64;
    const int warp_n = (wid >> 1) * 64;

    // ldmatrix per-lane addressing (swizzled)
    const uint32_t lrow = (uint32_t)(lane & 15);
    const uint32_t lxor = (uint32_t)((lane & 7) << 4);
    const uint32_t cbase = (uint32_t)((lane >> 4) * 16);
    const uint32_t aA = sbase + (uint32_t)((warp_m + (int)lrow) * ROW_BYTES);
    const uint32_t aB = sbase + (uint32_t)TILE_BYTES
                      + (uint32_t)((warp_n + (int)lrow) * ROW_BYTES);

    float acc[4][8][4];
#pragma unroll
    for (int i = 0; i < 4; i++)
#pragma unroll
        for (int j = 0; j < 8; j++)
#pragma unroll
            for (int q = 0; q < 4; q++) acc[i][j][q] = 0.f;

    // Prologue: fill 2 of 3 stages
    load_chunk(0, 0);
    load_chunk(1, 1);

    int s = 0;       // stage holding chunk c
    int s2 = 2;      // stage to load chunk c+2 into
    for (int c = 0; c < NCHUNK; c++) {
        if (c < NCHUNK - 1)
            asm volatile("cp.async.wait_group 1;" ::: "memory");
        else
            asm volatile("cp.async.wait_group 0;" ::: "memory");
        __syncthreads();

        if (c + 2 < NCHUNK) load_chunk(c + 2, s2);

        const uint32_t so = (uint32_t)(s * STAGE_BYTES);
#pragma unroll
        for (int ks = 0; ks < 4; ks++) {           // four k16 steps per chunk
            const uint32_t csw = ((uint32_t)(ks * 32) + cbase) ^ lxor;
            uint32_t a[4][4];
#pragma unroll
            for (int mt = 0; mt < 4; mt++)
                ldmatrix_x4(a[mt][0], a[mt][1], a[mt][2], a[mt][3],
                            aA + so + (uint32_t)(mt * 16 * ROW_BYTES) + csw);
            uint32_t b[8][2];
#pragma unroll
            for (int nt2 = 0; nt2 < 4; nt2++) {    // each covers n16 x k16
                uint32_t r0, r1, r2, r3;
                ldmatrix_x4(r0, r1, r2, r3,
                            aB + so + (uint32_t)(nt2 * 16 * ROW_BYTES) + csw);
                b[nt2 * 2 + 0][0] = r0; b[nt2 * 2 + 0][1] = r2;
                b[nt2 * 2 + 1][0] = r1; b[nt2 * 2 + 1][1] = r3;
            }
#pragma unroll
            for (int mt = 0; mt < 4; mt++)
#pragma unroll
                for (int nt = 0; nt < 8; nt++)
                    mma_16816(acc[mt][nt], a[mt], b[nt]);
        }

        s = (s == 2) ? 0 : s + 1;
        s2 = (s2 == 2) ? 0 : s2 + 1;
    }

    // Epilogue: scale + direct gmem stores.
    // mma C frag: row = lane>>2 (+0/+8), col = (lane&3)*2 (+0/+1)
    const int er = lane >> 2;
    const int ec = (lane & 3) * 2;
#pragma unroll
    for (int mt = 0; mt < 4; mt++) {
#pragma unroll
        for (int half = 0; half < 2; half++) {
            int m = m0 + warp_m + mt * 16 + half * 8 + er;
            float* orow = out + (size_t)m * N + n0 + warp_n + ec;
#pragma unroll
            for (int nt = 0; nt < 8; nt++) {
                float2 v;
                v.x = acc[mt][nt][half * 2 + 0] * scl;
                v.y = acc[mt][nt][half * 2 + 1] * scl;
                *reinterpret_cast<float2*>(orow + nt * 8) = v;
            }
        }
    }
}

// ---------------------------------------------------------------------------
// Launch
// ---------------------------------------------------------------------------
extern "C" void kernel_launch(void* const* d_in, const int* in_sizes, int n_in,
                              void* d_out, int out_size) {
    const float* x = (const float*)d_in[0];       // [4,2048,4096] fp32
    const int* w = (const int*)d_in[1];           // [11008,4096] int32
    const float* scale = (const float*)d_in[2];   // [1] fp32
    float* out = (float*)d_out;                   // [4,2048,11008] fp32
    (void)in_sizes; (void)n_in; (void)out_size;

    prepack_kernel<<<XB + WB, 256>>>((const float4*)x, (const int4*)w);

    cudaFuncSetAttribute(gemm_kernel,
                         cudaFuncAttributeMaxDynamicSharedMemorySize,
                         SMEM_BYTES);
    gemm_kernel<<<MT * NT, 128, SMEM_BYTES>>>(scale, out);
}